// round 12
// baseline (speedup 1.0000x reference)
#include <cuda_runtime.h>
#include <cuda_fp16.h>
#include <cstdint>

#define BN 65536
#define CN 128
#define DN 32
#define KN 10
#define EPSV 1e-12f
#define NCH 18            // 576 features / 32 per stage
#define ROWB 80           // 32 fp16 (64B) + 16B pad; conflict-free ldmatrix
#define SLAB 10240        // 128 rows * 80B, one split-stage image
#define SLAB2 20480       // 2 splits
#define STAGEB 40960      // A(2 splits) + B(2 splits) per ring stage
#define NRING 3

// Pre-split coefficient images: [split 0..1][stage 0..17][row=cluster][80B]. 360 KB, L2-resident.
__device__ unsigned char g_Wb[2 * NCH * SLAB];

// ---- dynamic smem layout ----
#define SM_ZS   0                     // 128 samples * 33 floats (stride 33)
#define SM_SCLS 16896                 // 128 int
#define SM_LUT4 17408                 // 288 uchar4 (feature pairs)
#define SM_RING 18560                 // NRING x STAGEB ring (also epilogue partials)
#define SMEM_DYN (SM_RING + NRING * STAGEB)   // 141440 B -> 1 CTA/SM

__device__ __forceinline__ uint32_t smem_u32(const void* p) {
    uint32_t a;
    asm("{ .reg .u64 t; cvta.to.shared.u64 t, %1; cvt.u32.u64 %0, t; }" : "=r"(a) : "l"(p));
    return a;
}
__device__ __forceinline__ void ldm_x4(uint32_t& r0, uint32_t& r1, uint32_t& r2, uint32_t& r3,
                                       uint32_t addr) {
    asm volatile("ldmatrix.sync.aligned.m8n8.x4.shared.b16 {%0,%1,%2,%3}, [%4];"
                 : "=r"(r0), "=r"(r1), "=r"(r2), "=r"(r3) : "r"(addr));
}
__device__ __forceinline__ void mma16816(float* d, const uint32_t* a, uint32_t b0, uint32_t b1) {
    asm volatile("mma.sync.aligned.m16n8k16.row.col.f32.f16.f16.f32 "
                 "{%0,%1,%2,%3}, {%4,%5,%6,%7}, {%8,%9}, {%0,%1,%2,%3};"
                 : "+f"(d[0]), "+f"(d[1]), "+f"(d[2]), "+f"(d[3])
                 : "r"(a[0]), "r"(a[1]), "r"(a[2]), "r"(a[3]), "r"(b0), "r"(b1));
}
__device__ __forceinline__ void cpasync16(uint32_t dst, const void* src) {
    asm volatile("cp.async.cg.shared.global [%0], [%1], 16;" :: "r"(dst), "l"(src));
}
#define CP_COMMIT() asm volatile("cp.async.commit_group;" ::: "memory")
#define CP_WAIT0()  asm volatile("cp.async.wait_group 0;" ::: "memory")
#define BAR_SYNC(id)   asm volatile("bar.sync %0, 512;"   :: "r"(id) : "memory")
#define BAR_ARRIVE(id) asm volatile("bar.arrive %0, 512;" :: "r"(id) : "memory")

// ---------------------------------------------------------------------------
// Pre-kernel: C_c[i,j] = Mext[i][j] * (i==j ? 0.5 : 1), 2-way fp16 split (h + l).
// ---------------------------------------------------------------------------
__global__ void pre_kernel(const float* __restrict__ mu,
                           const float* __restrict__ S_inv) {
    int c = blockIdx.x, t = threadIdx.x;
    __shared__ float sSm[DN];
    __shared__ float sT3;
    const float* W = S_inv + (size_t)c * DN * DN;
    const float* m = mu + (size_t)c * DN;

    if (t < DN) {
        float a = 0.f;
        #pragma unroll
        for (int e = 0; e < DN; ++e) a = fmaf(W[t * DN + e], m[e], a);
        sSm[t] = a;
    }
    __syncthreads();
    if (t == 0) {
        float a = 0.f;
        #pragma unroll
        for (int d = 0; d < DN; ++d) a = fmaf(m[d], sSm[d], a);
        sT3 = a;
    }
    __syncthreads();

    for (int k = t; k < 576; k += 128) {
        float Cv = 0.f;
        if (k < 561) {
            int i = 0;
            while (i < 32 && k >= 33 * (i + 1) - ((i + 1) * i) / 2) ++i;
            int j = i + (k - (33 * i - (i * (i - 1)) / 2));
            float Mv;
            if (j < 32)        Mv = W[i * DN + j];
            else if (i < 32)   Mv = -sSm[i];
            else               Mv = sT3;
            Cv = (i == j) ? 0.5f * Mv : Mv;
        }
        __half h = __float2half_rn(Cv);
        float r1 = Cv - __half2float(h);
        __half l = __float2half_rn(r1);

        size_t rowoff = (size_t)(k >> 5) * SLAB + (size_t)c * ROWB + (size_t)(k & 31) * 2;
        *(__half*)(g_Wb + 0 * NCH * SLAB + rowoff) = h;
        *(__half*)(g_Wb + 1 * NCH * SLAB + rowoff) = l;
    }
    if (t < 36) {
        int sp = t / NCH, ch = t - sp * NCH;
        *(uint4*)(g_Wb + (size_t)(sp * NCH + ch) * SLAB + (size_t)c * ROWB + 64) =
            make_uint4(0, 0, 0, 0);
    }
}

// ---------------------------------------------------------------------------
// Main kernel: 512 CTAs x 512 threads. Warps 0-7 consumers (MMA only),
// warps 8-15 producers (feature build + cp.async B). 3-deep ring, named barriers.
// ---------------------------------------------------------------------------
__global__ __launch_bounds__(512, 1)
void egauss_hmma(const float* __restrict__ data,
                 const int* __restrict__ labels,
                 float* __restrict__ out,
                 int out_size) {
    extern __shared__ char smem[];
    float* zs = (float*)(smem + SM_ZS);
    int* scls = (int*)(smem + SM_SCLS);
    uchar4* lut4 = (uchar4*)(smem + SM_LUT4);
    float* part = (float*)(smem + SM_RING);   // epilogue partials (reuses ring)
    uint32_t sb = smem_u32(smem);

    int tid = threadIdx.x;
    int wid = tid >> 5, lane = tid & 31;

    // ---- init (all threads) ----
    for (int p = tid; p < 288; p += 512) {
        int idx[2][2];
        #pragma unroll
        for (int h = 0; h < 2; ++h) {
            int k = 2 * p + h, i = 0, j = 0;
            if (k < 561) {
                while (i < 32 && k >= 33 * (i + 1) - ((i + 1) * i) / 2) ++i;
                j = i + (k - (33 * i - (i * (i - 1)) / 2));
            }
            idx[h][0] = i; idx[h][1] = j;
        }
        lut4[p] = make_uchar4((unsigned char)idx[0][0], (unsigned char)idx[0][1],
                              (unsigned char)idx[1][0], (unsigned char)idx[1][1]);
    }
    if (tid < CN) {
        const int* row = labels + tid * KN;
        int kc = 0;
        #pragma unroll
        for (int k = 0; k < KN; ++k) if (row[k] != 0) kc = k;
        scls[tid] = kc;
    }
    if (tid < 256) {   // stage z tile: 128 samples x (32+1) floats, stride 33
        int zi = tid >> 1, zh = tid & 1;
        const float4* src = (const float4*)(data + ((size_t)blockIdx.x * 128 + zi) * DN + zh * 16);
        #pragma unroll
        for (int q = 0; q < 4; ++q) {
            float4 v = src[q];
            float* dst = zs + zi * 33 + zh * 16 + q * 4;
            dst[0] = v.x; dst[1] = v.y; dst[2] = v.z; dst[3] = v.w;
        }
        if (tid < 128) zs[tid * 33 + 32] = 1.f;
    }
    __syncthreads();

    if (wid >= 8) {
        // ================= PRODUCERS (warps 8-15) =================
        int ptid = tid - 256;
        int ps = ptid >> 1, phf = ptid & 1;
        const float* zrow = zs + ps * 33;

        for (int ch = 0; ch < NCH; ++ch) {
            int buf = ch % NRING;
            if (ch >= NRING) BAR_SYNC(4 + buf);           // wait consumers done with buf

            uint32_t stage = (uint32_t)(SM_RING + buf * STAGEB);

            // B coefficients: cp.async, 2 splits
            #pragma unroll
            for (int sp = 0; sp < 2; ++sp) {
                const unsigned char* gsrc = g_Wb + (size_t)(sp * NCH + ch) * SLAB;
                uint32_t dbase = sb + stage + (uint32_t)(SLAB2 + sp * SLAB);
                #pragma unroll
                for (int r = 0; r < 3; ++r) {
                    int idx = ptid + 256 * r;
                    if (idx < SLAB / 16)
                        cpasync16(dbase + (uint32_t)(idx * 16), gsrc + idx * 16);
                }
            }
            CP_COMMIT();

            // A features: thread (ps, phf) builds 16 features of row ps
            {
                int pb = ch * 16 + phf * 8;
                unsigned hw[8], lw[8];
                #pragma unroll
                for (int p = 0; p < 8; ++p) {
                    uchar4 e = lut4[pb + p];
                    float f0 = zrow[e.x] * zrow[e.y];
                    float f1 = zrow[e.z] * zrow[e.w];
                    __half2 h2 = __floats2half2_rn(f0, f1);
                    float r0 = f0 - __low2float(h2);
                    float r1 = f1 - __high2float(h2);
                    __half2 l2 = __floats2half2_rn(r0, r1);
                    hw[p] = *reinterpret_cast<unsigned*>(&h2);
                    lw[p] = *reinterpret_cast<unsigned*>(&l2);
                }
                char* ab = smem + stage + ps * ROWB + phf * 32;
                *(uint4*)(ab + 0 * SLAB)      = make_uint4(hw[0], hw[1], hw[2], hw[3]);
                *(uint4*)(ab + 0 * SLAB + 16) = make_uint4(hw[4], hw[5], hw[6], hw[7]);
                *(uint4*)(ab + 1 * SLAB)      = make_uint4(lw[0], lw[1], lw[2], lw[3]);
                *(uint4*)(ab + 1 * SLAB + 16) = make_uint4(lw[4], lw[5], lw[6], lw[7]);
            }

            CP_WAIT0();
            __threadfence_block();                        // drain STS before arrive
            BAR_ARRIVE(1 + buf);                          // full[buf]
        }
    } else {
        // ================= CONSUMERS (warps 0-7) =================
        int wm = wid & 3, wn = wid >> 2;

        float acc[2][8][4];
        #pragma unroll
        for (int mt = 0; mt < 2; ++mt)
            #pragma unroll
            for (int g = 0; g < 8; ++g)
                #pragma unroll
                for (int q = 0; q < 4; ++q) acc[mt][g][q] = 0.f;

        uint32_t a_row = (uint32_t)(wm * 32 + (lane & 15));
        uint32_t a_colb = (uint32_t)((lane >> 4) * 16);
        uint32_t b_row = (uint32_t)(wn * 64 + (lane & 7) + ((lane & 16) ? 8 : 0));
        uint32_t b_colb = (uint32_t)((lane & 8) ? 16 : 0);

        for (int ch = 0; ch < NCH; ++ch) {
            int buf = ch % NRING;
            BAR_SYNC(1 + buf);                            // wait full[buf]

            uint32_t stage = sb + (uint32_t)(SM_RING + buf * STAGEB);

            #pragma unroll
            for (int ks = 0; ks < 2; ++ks) {
                uint32_t aAddr = stage + a_row * ROWB + a_colb + (uint32_t)(ks * 32);
                uint32_t ah[2][4], al[2][4];
                #pragma unroll
                for (int mt = 0; mt < 2; ++mt) {
                    ldm_x4(ah[mt][0], ah[mt][1], ah[mt][2], ah[mt][3],
                           aAddr + (uint32_t)(mt * 16 * ROWB) + 0 * SLAB);
                    ldm_x4(al[mt][0], al[mt][1], al[mt][2], al[mt][3],
                           aAddr + (uint32_t)(mt * 16 * ROWB) + 1 * SLAB);
                }

                #pragma unroll
                for (int nt2 = 0; nt2 < 4; ++nt2) {
                    uint32_t bAddr = stage + SLAB2
                                   + (uint32_t)(nt2 * 16) * ROWB + b_row * ROWB + b_colb
                                   + (uint32_t)(ks * 32);
                    uint32_t bh[4], bl[4];
                    ldm_x4(bh[0], bh[1], bh[2], bh[3], bAddr + 0 * SLAB);
                    ldm_x4(bl[0], bl[1], bl[2], bl[3], bAddr + 1 * SLAB);

                    #pragma unroll
                    for (int mt = 0; mt < 2; ++mt) {
                        float* d0 = acc[mt][2 * nt2];
                        float* d1 = acc[mt][2 * nt2 + 1];
                        mma16816(d0, ah[mt], bh[0], bh[1]);  mma16816(d1, ah[mt], bh[2], bh[3]);
                        mma16816(d0, al[mt], bh[0], bh[1]);  mma16816(d1, al[mt], bh[2], bh[3]);
                        mma16816(d0, ah[mt], bl[0], bl[1]);  mma16816(d1, ah[mt], bl[2], bl[3]);
                    }
                }
            }

            BAR_ARRIVE(4 + buf);                          // empty[buf]
        }

        // ---- epilogue pass 1 (consumers hold acc) -- deferred write below ----
        int q = lane & 3, rA = lane >> 2;
        __syncthreads();   // join: producers done; ring reusable as partials
        #pragma unroll
        for (int mt = 0; mt < 2; ++mt) {
            float scA[KN], scB[KN];
            #pragma unroll
            for (int k = 0; k < KN; ++k) { scA[k] = 0.f; scB[k] = 0.f; }
            float gsumA = 0.f, gsumB = 0.f, bestA = -1.f, bestB = -1.f;
            int cbA = 0, cbB = 0;

            #pragma unroll
            for (int g = 0; g < 8; ++g) {
                int c0 = wn * 64 + g * 8 + q * 2;
                float gA0 = __expf(-acc[mt][g][0]);
                float gA1 = __expf(-acc[mt][g][1]);
                float gB0 = __expf(-acc[mt][g][2]);
                float gB1 = __expf(-acc[mt][g][3]);
                gsumA += gA0 + gA1;  gsumB += gB0 + gB1;
                if (gA0 > bestA) { bestA = gA0; cbA = c0; }
                if (gA1 > bestA) { bestA = gA1; cbA = c0 + 1; }
                if (gB0 > bestB) { bestB = gB0; cbB = c0; }
                if (gB1 > bestB) { bestB = gB1; cbB = c0 + 1; }
                int k0 = scls[c0], k1 = scls[c0 + 1];
                #pragma unroll
                for (int k = 0; k < KN; ++k) {
                    if (k0 == k) { scA[k] += gA0; scB[k] += gB0; }
                    if (k1 == k) { scA[k] += gA1; scB[k] += gB1; }
                }
            }

            #pragma unroll
            for (int d = 1; d <= 2; d <<= 1) {
                gsumA += __shfl_xor_sync(0xffffffffu, gsumA, d);
                gsumB += __shfl_xor_sync(0xffffffffu, gsumB, d);
                #pragma unroll
                for (int k = 0; k < KN; ++k) {
                    scA[k] += __shfl_xor_sync(0xffffffffu, scA[k], d);
                    scB[k] += __shfl_xor_sync(0xffffffffu, scB[k], d);
                }
                float obA = __shfl_xor_sync(0xffffffffu, bestA, d);
                int ocA = __shfl_xor_sync(0xffffffffu, cbA, d);
                if (obA > bestA || (obA == bestA && ocA < cbA)) { bestA = obA; cbA = ocA; }
                float obB = __shfl_xor_sync(0xffffffffu, bestB, d);
                int ocB = __shfl_xor_sync(0xffffffffu, cbB, d);
                if (obB > bestB || (obB == bestB && ocB < cbB)) { bestB = obB; cbB = ocB; }
            }

            if (q == 0) {
                int r0 = wm * 32 + mt * 16 + rA;
                float* pA = part + (size_t)(wn * 128 + r0) * 13;
                #pragma unroll
                for (int k = 0; k < KN; ++k) pA[k] = scA[k];
                pA[10] = gsumA; pA[11] = bestA; pA[12] = (float)cbA;
                float* pB = part + (size_t)(wn * 128 + r0 + 8) * 13;
                #pragma unroll
                for (int k = 0; k < KN; ++k) pB[k] = scB[k];
                pB[10] = gsumB; pB[11] = bestB; pB[12] = (float)cbB;
            }
        }
    }
    if (wid >= 8) __syncthreads();   // producers join the same barrier as consumers' join
    __syncthreads();                 // partials visible to all

    // ---- epilogue pass 2: combine halves, normalize, argmax, write ----
    if (tid < 128) {
        const float* p0 = part + (size_t)tid * 13;
        const float* p1 = part + (size_t)(128 + tid) * 13;
        float gsum = p0[10] + p1[10];
        float inv = 1.f / (gsum + EPSV);

        long b = (long)blockIdx.x * 128 + tid;
        float* os = out + b * KN;
        float sbv = -1.f; int pb = 0;
        #pragma unroll
        for (int k = 0; k < KN; ++k) {
            float sv = (p0[k] + p1[k]) * inv;
            os[k] = sv;
            if (sv > sbv) { sbv = sv; pb = k; }
        }
        float cb = (p1[11] > p0[11]) ? p1[12] : p0[12];   // half0 wins ties (lower index)
        long bb = (long)BN * KN;
        if (out_size >= bb + BN)      out[bb + b] = (float)pb;
        if (out_size >= bb + 2 * BN)  out[bb + BN + b] = cb;
    }
}

extern "C" void kernel_launch(void* const* d_in, const int* in_sizes, int n_in,
                              void* d_out, int out_size) {
    const float* data   = (const float*)d_in[0];
    const float* mu     = (const float*)d_in[1];
    const float* S_inv  = (const float*)d_in[2];
    const int*   labels = (const int*)d_in[3];

    cudaFuncSetAttribute(egauss_hmma, cudaFuncAttributeMaxDynamicSharedMemorySize, SMEM_DYN);
    pre_kernel<<<CN, 128>>>(mu, S_inv);
    egauss_hmma<<<BN / 128, 512, SMEM_DYN>>>(data, labels, (float*)d_out, out_size);
}

// round 15
// speedup vs baseline: 1.0855x; 1.0855x over previous
#include <cuda_runtime.h>
#include <cuda_fp16.h>
#include <cstdint>

#define BN 65536
#define CN 128
#define DN 32
#define KN 10
#define EPSV 1e-12f
#define NCH 18            // 576 features / 32 per stage
#define ROWB 80           // 32 fp16 (64B) + 16B pad; conflict-free ldmatrix
#define SLAB 10240        // 128 rows * 80B, one split-stage image
#define SLAB2 20480       // 2 splits

// Pre-split coefficient images: [split 0..1][stage 0..17][row=cluster][80B]. 360 KB, L2-resident.
__device__ unsigned char g_Wb[2 * NCH * SLAB];

// ---- dynamic smem layout ----
#define SM_ZS   0                     // 128 samples * 33 floats (stride 33)
#define SM_SCLS 16896                 // 128 int
#define SM_LUT4 17408                 // 288 uchar4 (feature pairs)
#define SM_A    18560                 // 2 buffers x 2*SLAB feature images (also epilogue partials)
#define SM_B    (SM_A + 2 * SLAB2)    // 2 buffers x 2*SLAB coefficient images
#define SMEM_DYN (SM_B + 2 * SLAB2)   // 100480 B -> 2 CTAs/SM

__device__ __forceinline__ uint32_t smem_u32(const void* p) {
    uint32_t a;
    asm("{ .reg .u64 t; cvta.to.shared.u64 t, %1; cvt.u32.u64 %0, t; }" : "=r"(a) : "l"(p));
    return a;
}
__device__ __forceinline__ void ldm_x4(uint32_t& r0, uint32_t& r1, uint32_t& r2, uint32_t& r3,
                                       uint32_t addr) {
    asm volatile("ldmatrix.sync.aligned.m8n8.x4.shared.b16 {%0,%1,%2,%3}, [%4];"
                 : "=r"(r0), "=r"(r1), "=r"(r2), "=r"(r3) : "r"(addr));
}
__device__ __forceinline__ void mma16816(float* d, const uint32_t* a, uint32_t b0, uint32_t b1) {
    asm volatile("mma.sync.aligned.m16n8k16.row.col.f32.f16.f16.f32 "
                 "{%0,%1,%2,%3}, {%4,%5,%6,%7}, {%8,%9}, {%0,%1,%2,%3};"
                 : "+f"(d[0]), "+f"(d[1]), "+f"(d[2]), "+f"(d[3])
                 : "r"(a[0]), "r"(a[1]), "r"(a[2]), "r"(a[3]), "r"(b0), "r"(b1));
}
__device__ __forceinline__ void cpasync16(uint32_t dst, const void* src) {
    asm volatile("cp.async.cg.shared.global [%0], [%1], 16;" :: "r"(dst), "l"(src));
}
#define CP_COMMIT() asm volatile("cp.async.commit_group;" ::: "memory")
#define CP_WAIT0()  asm volatile("cp.async.wait_group 0;" ::: "memory")

// ---------------------------------------------------------------------------
// Pre-kernel: C_c[i,j] = Mext[i][j] * (i==j ? 0.5 : 1), 2-way fp16 split (h + l).
// ---------------------------------------------------------------------------
__global__ void pre_kernel(const float* __restrict__ mu,
                           const float* __restrict__ S_inv) {
    int c = blockIdx.x, t = threadIdx.x;
    __shared__ float sSm[DN];
    __shared__ float sT3;
    const float* W = S_inv + (size_t)c * DN * DN;
    const float* m = mu + (size_t)c * DN;

    if (t < DN) {
        float a = 0.f;
        #pragma unroll
        for (int e = 0; e < DN; ++e) a = fmaf(W[t * DN + e], m[e], a);
        sSm[t] = a;
    }
    __syncthreads();
    if (t == 0) {
        float a = 0.f;
        #pragma unroll
        for (int d = 0; d < DN; ++d) a = fmaf(m[d], sSm[d], a);
        sT3 = a;
    }
    __syncthreads();

    for (int k = t; k < 576; k += 128) {
        float Cv = 0.f;
        if (k < 561) {
            int i = 0;
            while (i < 32 && k >= 33 * (i + 1) - ((i + 1) * i) / 2) ++i;
            int j = i + (k - (33 * i - (i * (i - 1)) / 2));
            float Mv;
            if (j < 32)        Mv = W[i * DN + j];
            else if (i < 32)   Mv = -sSm[i];
            else               Mv = sT3;
            Cv = (i == j) ? 0.5f * Mv : Mv;
        }
        __half h = __float2half_rn(Cv);
        float r1 = Cv - __half2float(h);
        __half l = __float2half_rn(r1);

        size_t rowoff = (size_t)(k >> 5) * SLAB + (size_t)c * ROWB + (size_t)(k & 31) * 2;
        *(__half*)(g_Wb + 0 * NCH * SLAB + rowoff) = h;
        *(__half*)(g_Wb + 1 * NCH * SLAB + rowoff) = l;
    }
    if (t < 36) {
        int sp = t / NCH, ch = t - sp * NCH;
        *(uint4*)(g_Wb + (size_t)(sp * NCH + ch) * SLAB + (size_t)c * ROWB + 64) =
            make_uint4(0, 0, 0, 0);
    }
}

// ---------------------------------------------------------------------------
// Main kernel: 512 CTAs x 256 threads; warp tile 32(M)x64(N); K=32 per stage;
// product-major MMA ordering (same-acc reuse distance 16).
// ---------------------------------------------------------------------------
__global__ __launch_bounds__(256, 2)
void egauss_hmma(const float* __restrict__ data,
                 const int* __restrict__ labels,
                 float* __restrict__ out,
                 int out_size) {
    extern __shared__ char smem[];
    float* zs = (float*)(smem + SM_ZS);
    int* scls = (int*)(smem + SM_SCLS);
    uchar4* lut4 = (uchar4*)(smem + SM_LUT4);
    float* part = (float*)(smem + SM_A);   // epilogue partials
    uint32_t sb = smem_u32(smem);

    int tid = threadIdx.x;
    int wid = tid >> 5, lane = tid & 31;
    int wm = wid & 3, wn = wid >> 2;
    int s = tid >> 1, hf = tid & 1;

    for (int p = tid; p < 288; p += 256) {
        int idx[2][2];
        #pragma unroll
        for (int h = 0; h < 2; ++h) {
            int k = 2 * p + h, i = 0, j = 0;
            if (k < 561) {
                while (i < 32 && k >= 33 * (i + 1) - ((i + 1) * i) / 2) ++i;
                j = i + (k - (33 * i - (i * (i - 1)) / 2));
            }
            idx[h][0] = i; idx[h][1] = j;
        }
        lut4[p] = make_uchar4((unsigned char)idx[0][0], (unsigned char)idx[0][1],
                              (unsigned char)idx[1][0], (unsigned char)idx[1][1]);
    }
    if (tid < CN) {
        const int* row = labels + tid * KN;
        int kc = 0;
        #pragma unroll
        for (int k = 0; k < KN; ++k) if (row[k] != 0) kc = k;
        scls[tid] = kc;
    }
    {
        const float4* src = (const float4*)(data + ((size_t)blockIdx.x * 128 + s) * DN + hf * 16);
        #pragma unroll
        for (int q = 0; q < 4; ++q) {
            float4 v = src[q];
            float* dst = zs + s * 33 + hf * 16 + q * 4;
            dst[0] = v.x; dst[1] = v.y; dst[2] = v.z; dst[3] = v.w;
        }
        if (tid < 128) zs[tid * 33 + 32] = 1.f;
    }
    __syncthreads();

    const float* zrow = zs + s * 33;

#define COPY_B(CHI, BUF)                                                          \
    {                                                                             \
        _Pragma("unroll")                                                         \
        for (int sp = 0; sp < 2; ++sp) {                                          \
            const unsigned char* gsrc = g_Wb + (size_t)(sp * NCH + (CHI)) * SLAB; \
            uint32_t dbase = sb + SM_B + (BUF) * SLAB2 + sp * SLAB;               \
            _Pragma("unroll")                                                     \
            for (int r = 0; r < 3; ++r) {                                         \
                int idx = tid + 256 * r;                                          \
                if (idx < SLAB / 16)                                              \
                    cpasync16(dbase + (uint32_t)(idx * 16), gsrc + idx * 16);     \
            }                                                                     \
        }                                                                         \
        CP_COMMIT();                                                              \
    }

#define BUILD_A(CHI, BUF)                                                         \
    {                                                                             \
        int pb = (CHI) * 16 + hf * 8;                                             \
        unsigned hw[8], lw[8];                                                    \
        _Pragma("unroll")                                                         \
        for (int p = 0; p < 8; ++p) {                                             \
            uchar4 e = lut4[pb + p];                                              \
            float f0 = zrow[e.x] * zrow[e.y];                                     \
            float f1 = zrow[e.z] * zrow[e.w];                                     \
            __half2 h2 = __floats2half2_rn(f0, f1);                               \
            float r0 = f0 - __low2float(h2);                                      \
            float r1 = f1 - __high2float(h2);                                     \
            __half2 l2 = __floats2half2_rn(r0, r1);                               \
            hw[p] = *reinterpret_cast<unsigned*>(&h2);                            \
            lw[p] = *reinterpret_cast<unsigned*>(&l2);                            \
        }                                                                         \
        unsigned off = (unsigned)((BUF) * SLAB2 + s * ROWB + hf * 32);            \
        *(uint4*)(smem + SM_A + 0 * SLAB + off)      = make_uint4(hw[0], hw[1], hw[2], hw[3]); \
        *(uint4*)(smem + SM_A + 0 * SLAB + off + 16) = make_uint4(hw[4], hw[5], hw[6], hw[7]); \
        *(uint4*)(smem + SM_A + 1 * SLAB + off)      = make_uint4(lw[0], lw[1], lw[2], lw[3]); \
        *(uint4*)(smem + SM_A + 1 * SLAB + off + 16) = make_uint4(lw[4], lw[5], lw[6], lw[7]); \
    }

    float acc[2][8][4];
    #pragma unroll
    for (int mt = 0; mt < 2; ++mt)
        #pragma unroll
        for (int g = 0; g < 8; ++g)
            #pragma unroll
            for (int q = 0; q < 4; ++q) acc[mt][g][q] = 0.f;

    uint32_t a_row = (uint32_t)(wm * 32 + (lane & 15));
    uint32_t a_colb = (uint32_t)((lane >> 4) * 16);
    uint32_t b_row = (uint32_t)(wn * 64 + (lane & 7) + ((lane & 16) ? 8 : 0));
    uint32_t b_colb = (uint32_t)((lane & 8) ? 16 : 0);

    COPY_B(0, 0)
    BUILD_A(0, 0)
    CP_WAIT0();
    __syncthreads();

    for (int ch = 0; ch < NCH; ++ch) {
        int cur = ch & 1, nxt = cur ^ 1;

        if (ch + 1 < NCH) COPY_B(ch + 1, nxt)

        #pragma unroll
        for (int ks = 0; ks < 2; ++ks) {
            // ---- load ALL fragments for this k-step ----
            uint32_t aAddr = sb + SM_A + (uint32_t)(cur * SLAB2)
                           + a_row * ROWB + a_colb + (uint32_t)(ks * 32);
            uint32_t ah[2][4], al[2][4];
            #pragma unroll
            for (int mt = 0; mt < 2; ++mt) {
                ldm_x4(ah[mt][0], ah[mt][1], ah[mt][2], ah[mt][3],
                       aAddr + (uint32_t)(mt * 16 * ROWB) + 0 * SLAB);
                ldm_x4(al[mt][0], al[mt][1], al[mt][2], al[mt][3],
                       aAddr + (uint32_t)(mt * 16 * ROWB) + 1 * SLAB);
            }
            uint32_t bh[4][4], bl[4][4];
            #pragma unroll
            for (int nt2 = 0; nt2 < 4; ++nt2) {
                uint32_t bAddr = sb + SM_B + (uint32_t)(cur * SLAB2)
                               + (uint32_t)(nt2 * 16) * ROWB + b_row * ROWB + b_colb
                               + (uint32_t)(ks * 32);
                ldm_x4(bh[nt2][0], bh[nt2][1], bh[nt2][2], bh[nt2][3], bAddr + 0 * SLAB);
                ldm_x4(bl[nt2][0], bl[nt2][1], bl[nt2][2], bl[nt2][3], bAddr + 1 * SLAB);
            }

            // ---- product-major passes: same-acc reuse distance = 16 mmas ----
            // pass 1: hh
            #pragma unroll
            for (int nt2 = 0; nt2 < 4; ++nt2)
                #pragma unroll
                for (int mt = 0; mt < 2; ++mt) {
                    mma16816(acc[mt][2 * nt2],     ah[mt], bh[nt2][0], bh[nt2][1]);
                    mma16816(acc[mt][2 * nt2 + 1], ah[mt], bh[nt2][2], bh[nt2][3]);
                }
            // pass 2: lh
            #pragma unroll
            for (int nt2 = 0; nt2 < 4; ++nt2)
                #pragma unroll
                for (int mt = 0; mt < 2; ++mt) {
                    mma16816(acc[mt][2 * nt2],     al[mt], bh[nt2][0], bh[nt2][1]);
                    mma16816(acc[mt][2 * nt2 + 1], al[mt], bh[nt2][2], bh[nt2][3]);
                }
            // pass 3: hl
            #pragma unroll
            for (int nt2 = 0; nt2 < 4; ++nt2)
                #pragma unroll
                for (int mt = 0; mt < 2; ++mt) {
                    mma16816(acc[mt][2 * nt2],     ah[mt], bl[nt2][0], bl[nt2][1]);
                    mma16816(acc[mt][2 * nt2 + 1], ah[mt], bl[nt2][2], bl[nt2][3]);
                }
        }

        if (ch + 1 < NCH) BUILD_A(ch + 1, nxt)

        CP_WAIT0();
        __syncthreads();
    }
#undef COPY_B
#undef BUILD_A

    // ---- epilogue pass 1: per-warp partials over its 64-column half ----
    int q = lane & 3, rA = lane >> 2;

    #pragma unroll
    for (int mt = 0; mt < 2; ++mt) {
        float scA[KN], scB[KN];
        #pragma unroll
        for (int k = 0; k < KN; ++k) { scA[k] = 0.f; scB[k] = 0.f; }
        float gsumA = 0.f, gsumB = 0.f, bestA = -1.f, bestB = -1.f;
        int cbA = 0, cbB = 0;

        #pragma unroll
        for (int g = 0; g < 8; ++g) {
            int c0 = wn * 64 + g * 8 + q * 2;
            float gA0 = __expf(-acc[mt][g][0]);
            float gA1 = __expf(-acc[mt][g][1]);
            float gB0 = __expf(-acc[mt][g][2]);
            float gB1 = __expf(-acc[mt][g][3]);
            gsumA += gA0 + gA1;  gsumB += gB0 + gB1;
            if (gA0 > bestA) { bestA = gA0; cbA = c0; }
            if (gA1 > bestA) { bestA = gA1; cbA = c0 + 1; }
            if (gB0 > bestB) { bestB = gB0; cbB = c0; }
            if (gB1 > bestB) { bestB = gB1; cbB = c0 + 1; }
            int k0 = scls[c0], k1 = scls[c0 + 1];
            #pragma unroll
            for (int k = 0; k < KN; ++k) {
                if (k0 == k) { scA[k] += gA0; scB[k] += gB0; }
                if (k1 == k) { scA[k] += gA1; scB[k] += gB1; }
            }
        }

        #pragma unroll
        for (int d = 1; d <= 2; d <<= 1) {
            gsumA += __shfl_xor_sync(0xffffffffu, gsumA, d);
            gsumB += __shfl_xor_sync(0xffffffffu, gsumB, d);
            #pragma unroll
            for (int k = 0; k < KN; ++k) {
                scA[k] += __shfl_xor_sync(0xffffffffu, scA[k], d);
                scB[k] += __shfl_xor_sync(0xffffffffu, scB[k], d);
            }
            float obA = __shfl_xor_sync(0xffffffffu, bestA, d);
            int ocA = __shfl_xor_sync(0xffffffffu, cbA, d);
            if (obA > bestA || (obA == bestA && ocA < cbA)) { bestA = obA; cbA = ocA; }
            float obB = __shfl_xor_sync(0xffffffffu, bestB, d);
            int ocB = __shfl_xor_sync(0xffffffffu, cbB, d);
            if (obB > bestB || (obB == bestB && ocB < cbB)) { bestB = obB; cbB = ocB; }
        }

        if (q == 0) {
            int r0 = wm * 32 + mt * 16 + rA;
            float* pA = part + (size_t)(wn * 128 + r0) * 13;
            #pragma unroll
            for (int k = 0; k < KN; ++k) pA[k] = scA[k];
            pA[10] = gsumA; pA[11] = bestA; pA[12] = (float)cbA;
            float* pB = part + (size_t)(wn * 128 + r0 + 8) * 13;
            #pragma unroll
            for (int k = 0; k < KN; ++k) pB[k] = scB[k];
            pB[10] = gsumB; pB[11] = bestB; pB[12] = (float)cbB;
        }
    }
    __syncthreads();

    // ---- epilogue pass 2: combine halves, normalize, argmax, write ----
    if (tid < 128) {
        const float* p0 = part + (size_t)tid * 13;
        const float* p1 = part + (size_t)(128 + tid) * 13;
        float gsum = p0[10] + p1[10];
        float inv = 1.f / (gsum + EPSV);

        long b = (long)blockIdx.x * 128 + tid;
        float* os = out + b * KN;
        float sbv = -1.f; int pb = 0;
        #pragma unroll
        for (int k = 0; k < KN; ++k) {
            float sv = (p0[k] + p1[k]) * inv;
            os[k] = sv;
            if (sv > sbv) { sbv = sv; pb = k; }
        }
        float cb = (p1[11] > p0[11]) ? p1[12] : p0[12];
        long bb = (long)BN * KN;
        if (out_size >= bb + BN)      out[bb + b] = (float)pb;
        if (out_size >= bb + 2 * BN)  out[bb + BN + b] = cb;
    }
}

extern "C" void kernel_launch(void* const* d_in, const int* in_sizes, int n_in,
                              void* d_out, int out_size) {
    const float* data   = (const float*)d_in[0];
    const float* mu     = (const float*)d_in[1];
    const float* S_inv  = (const float*)d_in[2];
    const int*   labels = (const int*)d_in[3];

    cudaFuncSetAttribute(egauss_hmma, cudaFuncAttributeMaxDynamicSharedMemorySize, SMEM_DYN);
    pre_kernel<<<CN, 128>>>(mu, S_inv);
    egauss_hmma<<<BN / 128, 256, SMEM_DYN>>>(data, labels, (float*)d_out, out_size);
}

// round 17
// speedup vs baseline: 1.2361x; 1.1387x over previous
#include <cuda_runtime.h>
#include <cuda_fp16.h>
#include <cstdint>

#define BN 65536
#define CN 128
#define DN 32
#define KN 10
#define EPSV 1e-12f
#define NCH 36            // 576 features / 16 per stage
#define ROWB 48           // 16 fp16 (32B) + 16B pad; conflict-free ldmatrix
#define SLAB_A 3072       // 64 rows * 48B  (A: 64 samples)
#define SLAB_B 6144       // 128 rows * 48B (B: 128 clusters)
#define SLAB2A 6144       // 2 splits per buffer
#define SLAB2B 12288

// Pre-split coefficient images: [split 0..1][chunk 0..35][row=cluster][48B]. 432 KB, L2-resident.
__device__ unsigned char g_Wb[2 * NCH * SLAB_B];

// ---- dynamic smem layout (per 128-thread CTA; 4 CTAs/SM) ----
#define SM_ZS   0                       // 64 samples * 33 floats (stride 33) = 8448
#define SM_SCLS 8448                    // 128 int = 512
#define SM_LUT4 8960                    // 288 uchar4 = 1152
#define SM_A    10112                   // 2 buf x 2 splits x SLAB_A = 12288 (also epilogue partials)
#define SM_B    (SM_A + 2 * SLAB2A)     // 2 buf x 2 splits x SLAB_B = 24576
#define SMEM_DYN (SM_B + 2 * SLAB2B)    // 46976 B -> 4 CTAs/SM

__device__ __forceinline__ uint32_t smem_u32(const void* p) {
    uint32_t a;
    asm("{ .reg .u64 t; cvta.to.shared.u64 t, %1; cvt.u32.u64 %0, t; }" : "=r"(a) : "l"(p));
    return a;
}
__device__ __forceinline__ void ldm_x4(uint32_t& r0, uint32_t& r1, uint32_t& r2, uint32_t& r3,
                                       uint32_t addr) {
    asm volatile("ldmatrix.sync.aligned.m8n8.x4.shared.b16 {%0,%1,%2,%3}, [%4];"
                 : "=r"(r0), "=r"(r1), "=r"(r2), "=r"(r3) : "r"(addr));
}
__device__ __forceinline__ void mma16816(float* d, const uint32_t* a, uint32_t b0, uint32_t b1) {
    asm volatile("mma.sync.aligned.m16n8k16.row.col.f32.f16.f16.f32 "
                 "{%0,%1,%2,%3}, {%4,%5,%6,%7}, {%8,%9}, {%0,%1,%2,%3};"
                 : "+f"(d[0]), "+f"(d[1]), "+f"(d[2]), "+f"(d[3])
                 : "r"(a[0]), "r"(a[1]), "r"(a[2]), "r"(a[3]), "r"(b0), "r"(b1));
}
__device__ __forceinline__ void cpasync16(uint32_t dst, const void* src) {
    asm volatile("cp.async.cg.shared.global [%0], [%1], 16;" :: "r"(dst), "l"(src));
}
#define CP_COMMIT() asm volatile("cp.async.commit_group;" ::: "memory")
#define CP_WAIT0()  asm volatile("cp.async.wait_group 0;" ::: "memory")

// ---------------------------------------------------------------------------
// Pre-kernel: C_c[i,j] = Mext[i][j] * (i==j ? 0.5 : 1), 2-way fp16 split (h + l).
// ---------------------------------------------------------------------------
__global__ void pre_kernel(const float* __restrict__ mu,
                           const float* __restrict__ S_inv) {
    int c = blockIdx.x, t = threadIdx.x;
    __shared__ float sSm[DN];
    __shared__ float sT3;
    const float* W = S_inv + (size_t)c * DN * DN;
    const float* m = mu + (size_t)c * DN;

    if (t < DN) {
        float a = 0.f;
        #pragma unroll
        for (int e = 0; e < DN; ++e) a = fmaf(W[t * DN + e], m[e], a);
        sSm[t] = a;
    }
    __syncthreads();
    if (t == 0) {
        float a = 0.f;
        #pragma unroll
        for (int d = 0; d < DN; ++d) a = fmaf(m[d], sSm[d], a);
        sT3 = a;
    }
    __syncthreads();

    for (int k = t; k < 576; k += 128) {
        float Cv = 0.f;
        if (k < 561) {
            int i = 0;
            while (i < 32 && k >= 33 * (i + 1) - ((i + 1) * i) / 2) ++i;
            int j = i + (k - (33 * i - (i * (i - 1)) / 2));
            float Mv;
            if (j < 32)        Mv = W[i * DN + j];
            else if (i < 32)   Mv = -sSm[i];
            else               Mv = sT3;
            Cv = (i == j) ? 0.5f * Mv : Mv;
        }
        __half h = __float2half_rn(Cv);
        float r1 = Cv - __half2float(h);
        __half l = __float2half_rn(r1);

        size_t rowoff = (size_t)(k >> 4) * SLAB_B + (size_t)c * ROWB + (size_t)(k & 15) * 2;
        *(__half*)(g_Wb + 0 * NCH * SLAB_B + rowoff) = h;
        *(__half*)(g_Wb + 1 * NCH * SLAB_B + rowoff) = l;
    }
    if (t < 72) {
        int sp = t / NCH, ch = t - sp * NCH;
        *(uint4*)(g_Wb + (size_t)(sp * NCH + ch) * SLAB_B + (size_t)c * ROWB + 32) =
            make_uint4(0, 0, 0, 0);
    }
}

// ---------------------------------------------------------------------------
// Main kernel: 1024 CTAs x 128 threads (4 warps, 32x64 warp tiles); CTA tile
// 64 samples x 128 clusters; K=16 stages; fp16 2-split, 3-product pyramid;
// 4 CTAs/SM -> independent sync domains decorrelate barrier/build stalls.
// ---------------------------------------------------------------------------
__global__ __launch_bounds__(128, 4)
void egauss_hmma(const float* __restrict__ data,
                 const int* __restrict__ labels,
                 float* __restrict__ out,
                 int out_size) {
    extern __shared__ char smem[];
    float* zs = (float*)(smem + SM_ZS);
    int* scls = (int*)(smem + SM_SCLS);
    uchar4* lut4 = (uchar4*)(smem + SM_LUT4);
    float* part = (float*)(smem + SM_A);   // epilogue partials (reuses A ring)
    uint32_t sb = smem_u32(smem);

    int tid = threadIdx.x;
    int wid = tid >> 5, lane = tid & 31;
    int wm = wid & 1, wn = wid >> 1;       // warp tile: rows wm*32.., cols wn*64..
    int s = tid >> 1, hf = tid & 1;        // s: sample row 0..63

    // feature-pair LUT: entry p -> (i,j) of features 2p and 2p+1 (pad -> (0,0))
    for (int p = tid; p < 288; p += 128) {
        int idx[2][2];
        #pragma unroll
        for (int h = 0; h < 2; ++h) {
            int k = 2 * p + h, i = 0, j = 0;
            if (k < 561) {
                while (i < 32 && k >= 33 * (i + 1) - ((i + 1) * i) / 2) ++i;
                j = i + (k - (33 * i - (i * (i - 1)) / 2));
            }
            idx[h][0] = i; idx[h][1] = j;
        }
        lut4[p] = make_uchar4((unsigned char)idx[0][0], (unsigned char)idx[0][1],
                              (unsigned char)idx[1][0], (unsigned char)idx[1][1]);
    }
    if (tid < CN) {
        const int* row = labels + tid * KN;
        int kc = 0;
        #pragma unroll
        for (int k = 0; k < KN; ++k) if (row[k] != 0) kc = k;
        scls[tid] = kc;
    }
    // stage z tile: 64 samples x (32+1) floats, stride 33
    {
        const float4* src = (const float4*)(data + ((size_t)blockIdx.x * 64 + s) * DN + hf * 16);
        #pragma unroll
        for (int q = 0; q < 4; ++q) {
            float4 v = src[q];
            float* dst = zs + s * 33 + hf * 16 + q * 4;
            dst[0] = v.x; dst[1] = v.y; dst[2] = v.z; dst[3] = v.w;
        }
        if (tid < 64) zs[tid * 33 + 32] = 1.f;
    }
    __syncthreads();

    const float* zrow = zs + s * 33;

#define COPY_B(CHI, BUF)                                                            \
    {                                                                               \
        _Pragma("unroll")                                                           \
        for (int sp = 0; sp < 2; ++sp) {                                            \
            const unsigned char* gsrc = g_Wb + (size_t)(sp * NCH + (CHI)) * SLAB_B; \
            uint32_t dbase = sb + SM_B + (BUF) * SLAB2B + sp * SLAB_B;              \
            _Pragma("unroll")                                                       \
            for (int r = 0; r < 3; ++r) {                                           \
                int idx = tid + 128 * r;                                            \
                cpasync16(dbase + (uint32_t)(idx * 16), gsrc + idx * 16);           \
            }                                                                       \
        }                                                                           \
        CP_COMMIT();                                                                \
    }

    // thread (s, hf) builds 8 features of row s: k = CHI*16 + hf*8 + 0..7
#define BUILD_A(CHI, BUF)                                                           \
    {                                                                               \
        int pb = (CHI) * 8 + hf * 4;                                                \
        unsigned hw[4], lw[4];                                                      \
        _Pragma("unroll")                                                           \
        for (int p = 0; p < 4; ++p) {                                               \
            uchar4 e = lut4[pb + p];                                                \
            float f0 = zrow[e.x] * zrow[e.y];                                       \
            float f1 = zrow[e.z] * zrow[e.w];                                       \
            __half2 h2 = __floats2half2_rn(f0, f1);                                 \
            float r0 = f0 - __low2float(h2);                                        \
            float r1 = f1 - __high2float(h2);                                       \
            __half2 l2 = __floats2half2_rn(r0, r1);                                 \
            hw[p] = *reinterpret_cast<unsigned*>(&h2);                              \
            lw[p] = *reinterpret_cast<unsigned*>(&l2);                              \
        }                                                                           \
        unsigned off = (unsigned)((BUF) * SLAB2A + s * ROWB + hf * 16);             \
        *(uint4*)(smem + SM_A + 0 * SLAB_A + off) = make_uint4(hw[0], hw[1], hw[2], hw[3]); \
        *(uint4*)(smem + SM_A + 1 * SLAB_A + off) = make_uint4(lw[0], lw[1], lw[2], lw[3]); \
    }

    float acc[2][8][4];
    #pragma unroll
    for (int mt = 0; mt < 2; ++mt)
        #pragma unroll
        for (int g = 0; g < 8; ++g)
            #pragma unroll
            for (int q = 0; q < 4; ++q) acc[mt][g][q] = 0.f;

    // ldmatrix addressing
    uint32_t a_row = (uint32_t)(wm * 32 + (lane & 15));
    uint32_t a_colb = (uint32_t)((lane >> 4) * 16);
    uint32_t b_row = (uint32_t)(wn * 64 + (lane & 7) + ((lane & 16) ? 8 : 0));
    uint32_t b_colb = (uint32_t)((lane & 8) ? 16 : 0);

    COPY_B(0, 0)
    BUILD_A(0, 0)
    CP_WAIT0();
    __syncthreads();

    for (int ch = 0; ch < NCH; ++ch) {
        int cur = ch & 1, nxt = cur ^ 1;

        if (ch + 1 < NCH) COPY_B(ch + 1, nxt)

        // A fragments for this stage (K=16): 2 M-subtiles x 2 splits
        uint32_t aAddr = sb + SM_A + (uint32_t)(cur * SLAB2A) + a_row * ROWB + a_colb;
        uint32_t ah[2][4], al[2][4];
        #pragma unroll
        for (int mt = 0; mt < 2; ++mt) {
            ldm_x4(ah[mt][0], ah[mt][1], ah[mt][2], ah[mt][3],
                   aAddr + (uint32_t)(mt * 16 * ROWB) + 0 * SLAB_A);
            ldm_x4(al[mt][0], al[mt][1], al[mt][2], al[mt][3],
                   aAddr + (uint32_t)(mt * 16 * ROWB) + 1 * SLAB_A);
        }

        // B in two halves (nt2 pairs) to bound registers; product-major inside
        #pragma unroll
        for (int bhv = 0; bhv < 2; ++bhv) {
            uint32_t bh[2][4], bl[2][4];
            #pragma unroll
            for (int t2 = 0; t2 < 2; ++t2) {
                int nt2 = bhv * 2 + t2;
                uint32_t bAddr = sb + SM_B + (uint32_t)(cur * SLAB2B)
                               + ((uint32_t)(nt2 * 16) + b_row) * ROWB + b_colb;
                ldm_x4(bh[t2][0], bh[t2][1], bh[t2][2], bh[t2][3], bAddr + 0 * SLAB_B);
                ldm_x4(bl[t2][0], bl[t2][1], bl[t2][2], bl[t2][3], bAddr + 1 * SLAB_B);
            }
            // pass 1: hh
            #pragma unroll
            for (int t2 = 0; t2 < 2; ++t2)
                #pragma unroll
                for (int mt = 0; mt < 2; ++mt) {
                    int g = (bhv * 2 + t2) * 2;
                    mma16816(acc[mt][g],     ah[mt], bh[t2][0], bh[t2][1]);
                    mma16816(acc[mt][g + 1], ah[mt], bh[t2][2], bh[t2][3]);
                }
            // pass 2: lh
            #pragma unroll
            for (int t2 = 0; t2 < 2; ++t2)
                #pragma unroll
                for (int mt = 0; mt < 2; ++mt) {
                    int g = (bhv * 2 + t2) * 2;
                    mma16816(acc[mt][g],     al[mt], bh[t2][0], bh[t2][1]);
                    mma16816(acc[mt][g + 1], al[mt], bh[t2][2], bh[t2][3]);
                }
            // pass 3: hl
            #pragma unroll
            for (int t2 = 0; t2 < 2; ++t2)
                #pragma unroll
                for (int mt = 0; mt < 2; ++mt) {
                    int g = (bhv * 2 + t2) * 2;
                    mma16816(acc[mt][g],     ah[mt], bl[t2][0], bl[t2][1]);
                    mma16816(acc[mt][g + 1], ah[mt], bl[t2][2], bl[t2][3]);
                }
        }

        if (ch + 1 < NCH) BUILD_A(ch + 1, nxt)

        CP_WAIT0();
        __syncthreads();
    }
#undef COPY_B
#undef BUILD_A

    // ---- epilogue pass 1: per-warp partials over its 64-column half ----
    int q = lane & 3, rA = lane >> 2;

    #pragma unroll
    for (int mt = 0; mt < 2; ++mt) {
        float scA[KN], scB[KN];
        #pragma unroll
        for (int k = 0; k < KN; ++k) { scA[k] = 0.f; scB[k] = 0.f; }
        float gsumA = 0.f, gsumB = 0.f, bestA = -1.f, bestB = -1.f;
        int cbA = 0, cbB = 0;

        #pragma unroll
        for (int g = 0; g < 8; ++g) {
            int c0 = wn * 64 + g * 8 + q * 2;
            float gA0 = __expf(-acc[mt][g][0]);
            float gA1 = __expf(-acc[mt][g][1]);
            float gB0 = __expf(-acc[mt][g][2]);
            float gB1 = __expf(-acc[mt][g][3]);
            gsumA += gA0 + gA1;  gsumB += gB0 + gB1;
            if (gA0 > bestA) { bestA = gA0; cbA = c0; }
            if (gA1 > bestA) { bestA = gA1; cbA = c0 + 1; }
            if (gB0 > bestB) { bestB = gB0; cbB = c0; }
            if (gB1 > bestB) { bestB = gB1; cbB = c0 + 1; }
            int k0 = scls[c0], k1 = scls[c0 + 1];
            #pragma unroll
            for (int k = 0; k < KN; ++k) {
                if (k0 == k) { scA[k] += gA0; scB[k] += gB0; }
                if (k1 == k) { scA[k] += gA1; scB[k] += gB1; }
            }
        }

        #pragma unroll
        for (int d = 1; d <= 2; d <<= 1) {
            gsumA += __shfl_xor_sync(0xffffffffu, gsumA, d);
            gsumB += __shfl_xor_sync(0xffffffffu, gsumB, d);
            #pragma unroll
            for (int k = 0; k < KN; ++k) {
                scA[k] += __shfl_xor_sync(0xffffffffu, scA[k], d);
                scB[k] += __shfl_xor_sync(0xffffffffu, scB[k], d);
            }
            float obA = __shfl_xor_sync(0xffffffffu, bestA, d);
            int ocA = __shfl_xor_sync(0xffffffffu, cbA, d);
            if (obA > bestA || (obA == bestA && ocA < cbA)) { bestA = obA; cbA = ocA; }
            float obB = __shfl_xor_sync(0xffffffffu, bestB, d);
            int ocB = __shfl_xor_sync(0xffffffffu, cbB, d);
            if (obB > bestB || (obB == bestB && ocB < cbB)) { bestB = obB; cbB = ocB; }
        }

        if (q == 0) {
            int r0 = wm * 32 + mt * 16 + rA;      // 0..63
            float* pA = part + (size_t)(wn * 64 + r0) * 13;
            #pragma unroll
            for (int k = 0; k < KN; ++k) pA[k] = scA[k];
            pA[10] = gsumA; pA[11] = bestA; pA[12] = (float)cbA;
            float* pB = part + (size_t)(wn * 64 + r0 + 8) * 13;
            #pragma unroll
            for (int k = 0; k < KN; ++k) pB[k] = scB[k];
            pB[10] = gsumB; pB[11] = bestB; pB[12] = (float)cbB;
        }
    }
    __syncthreads();

    // ---- epilogue pass 2: combine halves, normalize, argmax, write ----
    if (tid < 64) {
        const float* p0 = part + (size_t)tid * 13;
        const float* p1 = part + (size_t)(64 + tid) * 13;
        float gsum = p0[10] + p1[10];
        float inv = 1.f / (gsum + EPSV);

        long b = (long)blockIdx.x * 64 + tid;
        float* os = out + b * KN;
        float sbv = -1.f; int pb = 0;
        #pragma unroll
        for (int k = 0; k < KN; ++k) {
            float sv = (p0[k] + p1[k]) * inv;
            os[k] = sv;
            if (sv > sbv) { sbv = sv; pb = k; }
        }
        float cb = (p1[11] > p0[11]) ? p1[12] : p0[12];   // half0 wins ties (lower index)
        long bb = (long)BN * KN;
        if (out_size >= bb + BN)      out[bb + b] = (float)pb;
        if (out_size >= bb + 2 * BN)  out[bb + BN + b] = cb;
    }
}

extern "C" void kernel_launch(void* const* d_in, const int* in_sizes, int n_in,
                              void* d_out, int out_size) {
    const float* data   = (const float*)d_in[0];
    const float* mu     = (const float*)d_in[1];
    const float* S_inv  = (const float*)d_in[2];
    const int*   labels = (const int*)d_in[3];

    cudaFuncSetAttribute(egauss_hmma, cudaFuncAttributeMaxDynamicSharedMemorySize, SMEM_DYN);
    pre_kernel<<<CN, 128>>>(mu, S_inv);
    egauss_hmma<<<BN / 64, 128, SMEM_DYN>>>(data, labels, (float*)d_out, out_size);
}